// round 8
// baseline (speedup 1.0000x reference)
#include <cuda_runtime.h>
#include <cuda_bf16.h>
#include <cstdint>

#define BB 2
#define CC 32
#define DD 16
#define CKK 4
#define EE 64      // CKK*DD
#define MM 512     // CC*DD
#define NN 4096    // H*W

// ---------------- scratch (allocation-free device globals) -----------------
__device__ __align__(128) __nv_bfloat16 g_K[BB*NN*EE];        // [b][i][e] bf16
__device__ __align__(128) __nv_bfloat16 g_Q[BB*NN*EE];        // [b][j][e] bf16
__device__ __align__(128) uint8_t g_V8[(size_t)BB*MM*NN];     // [b][m][j] e4m3, perm rows
__device__ __align__(128) uint8_t g_P8[(size_t)BB*NN*NN];     // [b][i][j] e4m3, perm rows (32MB)
__device__ __align__(128) float g_rsum[BB*4*NN];              // [b][quarter][i]

// ---------------- helpers ---------------------------------------------------
__device__ __forceinline__ uint32_t smem_u32(const void* p) {
    uint32_t a;
    asm("{ .reg .u64 t; cvta.to.shared.u64 t, %1; cvt.u32.u64 %0, t; }"
        : "=r"(a) : "l"(p));
    return a;
}
// swizzled byte offset for (row, 16B-chunk) in a 128B-row bf16 tile
__device__ __forceinline__ uint32_t swoff(int r, int c) {
    return (uint32_t)(r * 128 + ((c ^ (r & 7)) << 4));
}
__device__ __forceinline__ void ldm_x4(uint32_t* r, uint32_t addr) {
    asm volatile("ldmatrix.sync.aligned.m8n8.x4.shared.b16 {%0,%1,%2,%3}, [%4];"
        : "=r"(r[0]), "=r"(r[1]), "=r"(r[2]), "=r"(r[3]) : "r"(addr));
}
__device__ __forceinline__ void mma_bf16(float* c, const uint32_t* a, const uint32_t* b) {
    asm volatile("mma.sync.aligned.m16n8k16.row.col.f32.bf16.bf16.f32 "
        "{%0,%1,%2,%3}, {%4,%5,%6,%7}, {%8,%9}, {%0,%1,%2,%3};"
        : "+f"(c[0]), "+f"(c[1]), "+f"(c[2]), "+f"(c[3])
        : "r"(a[0]), "r"(a[1]), "r"(a[2]), "r"(a[3]), "r"(b[0]), "r"(b[1]));
}
__device__ __forceinline__ void mma_fp8(float* c, uint32_t a0, uint32_t a1,
                                        uint32_t a2, uint32_t a3,
                                        uint32_t b0, uint32_t b1) {
    asm volatile("mma.sync.aligned.m16n8k32.row.col.f32.e4m3.e4m3.f32 "
        "{%0,%1,%2,%3}, {%4,%5,%6,%7}, {%8,%9}, {%0,%1,%2,%3};"
        : "+f"(c[0]), "+f"(c[1]), "+f"(c[2]), "+f"(c[3])
        : "r"(a0), "r"(a1), "r"(a2), "r"(a3), "r"(b0), "r"(b1));
}
__device__ __forceinline__ void lds128(uint32_t* r, uint32_t addr) {
    asm volatile("ld.shared.v4.b32 {%0,%1,%2,%3}, [%4];"
        : "=r"(r[0]), "=r"(r[1]), "=r"(r[2]), "=r"(r[3]) : "r"(addr));
}
__device__ __forceinline__ void cpasync16(uint32_t dst, const void* src) {
    asm volatile("cp.async.cg.shared.global [%0], [%1], 16;" :: "r"(dst), "l"(src));
}
// pack 2 floats -> e4m3x2 (lo byte = e0, hi byte = e1)
__device__ __forceinline__ unsigned short pack_e4m3x2(float e0, float e1) {
    unsigned short h;
    asm("cvt.rn.satfinite.e4m3x2.f32 %0, %1, %2;" : "=h"(h) : "f"(e1), "f"(e0));
    return h;
}
// fast exp: e^x = 2^(x*log2e), deg-4 poly, rel err ~5e-5
__device__ __forceinline__ float fast_exp(float x) {
    float t  = x * 1.4426950408889634f;
    float rn = (t + 12582912.0f) - 12582912.0f;
    float f  = t - rn;
    int   n  = (int)rn;
    float p = 0.00961812910762848f;
    p = fmaf(p, f, 0.0555041086648216f);
    p = fmaf(p, f, 0.2402265069591007f);
    p = fmaf(p, f, 0.6931471805599453f);
    p = fmaf(p, f, 1.0f);
    return __int_as_float(__float_as_int(p) + (n << 23));
}

// ---------------------------------------------------------------------------
// Projection: K/Q bf16 [b][i][e]; V fp8 [b][m][j] with 64B-block word perm.
// ---------------------------------------------------------------------------
__global__ __launch_bounds__(256) void rsa_proj_kernel(
    const float* __restrict__ x,
    const float* __restrict__ Wk, const float* __restrict__ bk,
    const float* __restrict__ Wq, const float* __restrict__ bq,
    const float* __restrict__ Wv, const float* __restrict__ bv)
{
    __shared__ float sX[CC*256];
    __shared__ float sWk[CKK*CC], sWq[CKK*CC], sWv[CC*CC];
    __shared__ float sbk[CKK], sbq[CKK], sbv[CC];
    const int tid = threadIdx.x;
    for (int t = tid; t < CKK*CC; t += 256) { sWk[t] = Wk[t]; sWq[t] = Wq[t]; }
    for (int t = tid; t < CC*CC; t += 256) sWv[t] = Wv[t];
    if (tid < CKK) { sbk[tid] = bk[tid]; sbq[tid] = bq[tid]; }
    if (tid < CC)  sbv[tid] = bv[tid];

    const int blk   = blockIdx.x;
    const int chunk = blk & 15;
    const int d     = (blk >> 4) & 15;
    const int b     = blk >> 8;
    const int ibase = chunk * 256;

#pragma unroll
    for (int f = 0; f < CC; f++)
        sX[f*256 + tid] = x[((size_t)(b*CC + f)*DD + d)*NN + ibase + tid];
    __syncthreads();

    const int i = tid;
    const int j = ibase + i;
    // permuted byte position within 64B block (along j)
    const int w  = (j >> 2) & 15, bb = j & 3;
    const int pj = (j & ~63) + (((w & 3) << 2) | (w >> 2)) * 4 + bb;

    {
        float ka[CKK], qa[CKK];
#pragma unroll
        for (int o = 0; o < CKK; o++) { ka[o] = sbk[o]; qa[o] = sbq[o]; }
#pragma unroll
        for (int c = 0; c < CC; c++) {
            float xv = sX[c*256 + i];
#pragma unroll
            for (int o = 0; o < CKK; o++) {
                ka[o] = fmaf(sWk[o*CC + c], xv, ka[o]);
                qa[o] = fmaf(sWq[o*CC + c], xv, qa[o]);
            }
        }
#pragma unroll
        for (int o = 0; o < CKK; o++) {
            g_K[(size_t)(b*NN + j)*EE + o*DD + d] = __float2bfloat16_rn(ka[o]);
            g_Q[(size_t)(b*NN + j)*EE + o*DD + d] = __float2bfloat16_rn(qa[o]);
        }
    }

#pragma unroll
    for (int gr = 0; gr < 4; gr++) {
        float va[8];
#pragma unroll
        for (int o = 0; o < 8; o++) va[o] = sbv[gr*8 + o];
#pragma unroll
        for (int c = 0; c < CC; c++) {
            float xv = sX[c*256 + i];
#pragma unroll
            for (int o = 0; o < 8; o++)
                va[o] = fmaf(sWv[(gr*8 + o)*CC + c], xv, va[o]);
        }
#pragma unroll
        for (int o = 0; o < 8; o++) {
            unsigned short h = pack_e4m3x2(va[o], 0.0f);
            g_V8[((size_t)(b*MM + (gr*8 + o)*DD + d))*NN + pj] = (uint8_t)(h & 0xFF);
        }
    }
}

// ---------------------------------------------------------------------------
// QK kernel: S = K_i Q_j^T (bf16 mma), P = exp(S) -> g_P8 (e4m3, perm rows).
// sP row = 64 u16 entries + 2 pad = 66 u16 (33 u32) stride.  [R7 bugfix]
// grid (32 i-tiles, 4 j-quarters, BB), 256 threads
// ---------------------------------------------------------------------------
#define QK_SM_K 0
#define QK_SM_Q 16384
#define QK_SM_P 32768                      // 128 rows x 132B
#define QK_SMEM (32768 + 128*132)          // 49664

__global__ __launch_bounds__(256, 2) void rsa_qk_kernel()
{
    extern __shared__ char smem[];
    const uint32_t sb = smem_u32(smem);
    unsigned short* sP16 = (unsigned short*)(smem + QK_SM_P);
    uint32_t*       sP32 = (uint32_t*)(smem + QK_SM_P);
    const int tid  = threadIdx.x;
    const int wid  = tid >> 5, lane = tid & 31;
    const int g    = lane >> 2, q = lane & 3;
    const int b    = blockIdx.z, ibase = blockIdx.x * 128, quart = blockIdx.y;
    const int wbase = wid * 16;

    for (int f = tid; f < 1024; f += 256) {
        int r = f >> 3, c = f & 7;
        *(float4*)(smem + QK_SM_K + swoff(r, c)) =
            *(const float4*)(g_K + (size_t)(b*NN + ibase + r)*EE + c*8);
    }
    __syncthreads();

    uint32_t afr[4][4];
    {
        int sg = lane >> 3, rr = lane & 7;
        int arow = wbase + ((sg & 1) << 3) + rr;
#pragma unroll
        for (int ks = 0; ks < 4; ks++)
            ldm_x4(afr[ks], sb + QK_SM_K + swoff(arow, 2*ks + (sg >> 1)));
    }

    const int brow = lane & 7, bco = lane >> 3;
    float rs0 = 0.f, rs1 = 0.f;

    for (int jt = 0; jt < 8; jt++) {
        const int jb = quart*1024 + jt*128;
        __syncthreads();
        for (int f = tid; f < 1024; f += 256) {
            int r = f >> 3, c = f & 7;
            *(float4*)(smem + QK_SM_Q + swoff(r, c)) =
                *(const float4*)(g_Q + (size_t)(b*NN + jb + r)*EE + c*8);
        }
        __syncthreads();

#pragma unroll
        for (int f = 0; f < 16; f++) {
            float acc[4] = {0.f, 0.f, 0.f, 0.f};
            uint32_t bfr[8];
            ldm_x4(bfr,     sb + QK_SM_Q + swoff(f*8 + brow, 0 + bco));
            ldm_x4(bfr + 4, sb + QK_SM_Q + swoff(f*8 + brow, 4 + bco));
            mma_bf16(acc, afr[0], bfr);
            mma_bf16(acc, afr[1], bfr + 2);
            mma_bf16(acc, afr[2], bfr + 4);
            mma_bf16(acc, afr[3], bfr + 6);
            float e0 = fast_exp(acc[0]), e1 = fast_exp(acc[1]);
            float e2 = fast_exp(acc[2]), e3 = fast_exp(acc[3]);
            rs0 += e0 + e1; rs1 += e2 + e3;
            sP16[(wbase + g    )*66 + f*4 + q] = pack_e4m3x2(e0, e1);
            sP16[(wbase + g + 8)*66 + f*4 + q] = pack_e4m3x2(e2, e3);
        }
        __syncthreads();
        // coalesced permuted copy-out: 128 rows x 32 u32 words (fp8)
        for (int f = tid; f < 4096; f += 256) {
            int r = f >> 5, c = f & 31;
            int blk2 = c >> 4, w = c & 15;
            uint32_t* dst = (uint32_t*)(g_P8 + (size_t)(b*NN + ibase + r)*NN + jb);
            dst[blk2*16 + (((w & 3) << 2) | (w >> 2))] = sP32[r*33 + c];
        }
    }

    rs0 += __shfl_xor_sync(0xffffffffu, rs0, 1);
    rs0 += __shfl_xor_sync(0xffffffffu, rs0, 2);
    rs1 += __shfl_xor_sync(0xffffffffu, rs1, 1);
    rs1 += __shfl_xor_sync(0xffffffffu, rs1, 2);
    if (q == 0) {
        g_rsum[(b*4 + quart)*NN + ibase + wbase + g]     = rs0;
        g_rsum[(b*4 + quart)*NN + ibase + wbase + g + 8] = rs1;
    }
}

// ---------------------------------------------------------------------------
// PV kernel (fp8 QMMA): D[128i,128m] = sum_j P[i,j] V[m,j].
// Flat 64B-stride fp8 tiles (rows pre-permuted in gmem), LDS.128 fragments,
// 2D warp tiling: 4 warps in i x 2 warps in m. Double-buffered cp.async.
// grid (32 i-tiles, 4 m-tiles, BB), 256 threads
// ---------------------------------------------------------------------------
#define PVF_STAGE 16384                     // A(8K) + B(8K)
#define PVF_SINV  (128*132*4)               // 67584
#define PVF_SMEM  (PVF_SINV + 512)

__global__ __launch_bounds__(256, 2) void rsa_pv_kernel(
    const float* __restrict__ x,
    const float* __restrict__ gamma,
    float* __restrict__ out)
{
    extern __shared__ char smem[];
    const uint32_t sb = smem_u32(smem);
    const int tid  = threadIdx.x;
    const int wid  = tid >> 5, lane = tid & 31;
    const int g    = lane >> 2, q = lane & 3;
    const int b    = blockIdx.z, ibase = blockIdx.x * 128, mbase = blockIdx.y * 128;
    const int wi   = wid & 3;          // i-group: rows wi*32 .. +31
    const int wm   = wid >> 2;         // m-half:  cols wm*64 .. +63

    auto load_chunk = [&](int c, int p) {
        const int jb = c * 64;
        const uint32_t sA = sb + p*PVF_STAGE;
        const uint32_t sB = sA + 8192;
#pragma unroll
        for (int it = 0; it < 2; it++) {
            int f = it*256 + tid;          // 0..511
            int r = f >> 2, cc = f & 3;
            cpasync16(sA + r*64 + cc*16,
                      g_P8 + (size_t)(b*NN + ibase + r)*NN + jb + cc*16);
            cpasync16(sB + r*64 + cc*16,
                      g_V8 + (size_t)(b*MM + mbase + r)*NN + jb + cc*16);
        }
        asm volatile("cp.async.commit_group;" ::: "memory");
    };

    float acc[2][8][4];
#pragma unroll
    for (int it = 0; it < 2; it++)
#pragma unroll
        for (int f = 0; f < 8; f++)
            acc[it][f][0] = acc[it][f][1] = acc[it][f][2] = acc[it][f][3] = 0.f;

    load_chunk(0, 0);

    for (int c = 0; c < 64; c++) {
        const int p = c & 1;
        if (c + 1 < 64) {
            load_chunk(c + 1, p ^ 1);
            asm volatile("cp.async.wait_group 1;" ::: "memory");
        } else {
            asm volatile("cp.async.wait_group 0;" ::: "memory");
        }
        __syncthreads();

        const uint32_t sA = sb + p*PVF_STAGE;
        const uint32_t sB = sA + 8192;

        // A fragments: 2 i-tiles, each 2 rows-of-8 x one LDS.128
        uint32_t ar[2][2][4];
#pragma unroll
        for (int it = 0; it < 2; it++) {
            uint32_t base = sA + (wi*32 + it*16 + g)*64 + 16*q;
            lds128(ar[it][0], base);
            lds128(ar[it][1], base + 8*64);
        }
#pragma unroll
        for (int f = 0; f < 8; f++) {
            uint32_t br[4];
            lds128(br, sB + (wm*64 + f*8 + g)*64 + 16*q);
#pragma unroll
            for (int it = 0; it < 2; it++) {
                mma_fp8(acc[it][f], ar[it][0][0], ar[it][1][0],
                                    ar[it][0][1], ar[it][1][1], br[0], br[1]);
                mma_fp8(acc[it][f], ar[it][0][2], ar[it][1][2],
                                    ar[it][0][3], ar[it][1][3], br[2], br[3]);
            }
        }
        __syncthreads();
    }

    // epilogue: rowsum inverses + stage D into smem
    float* sO   = (float*)smem;                 // [128 m][132]
    float* sInv = (float*)(smem + PVF_SINV);    // [128]
    if (tid < 128) {
        int i = ibase + tid;
        float rs = g_rsum[(b*4 + 0)*NN + i] + g_rsum[(b*4 + 1)*NN + i]
                 + g_rsum[(b*4 + 2)*NN + i] + g_rsum[(b*4 + 3)*NN + i];
        sInv[tid] = 1.0f / rs;
    }
#pragma unroll
    for (int it = 0; it < 2; it++) {
#pragma unroll
        for (int f = 0; f < 8; f++) {
            int m0 = wm*64 + f*8 + q*2;
            int il = wi*32 + it*16;
            sO[(m0    )*132 + il + g]     = acc[it][f][0];
            sO[(m0 + 1)*132 + il + g]     = acc[it][f][1];
            sO[(m0    )*132 + il + g + 8] = acc[it][f][2];
            sO[(m0 + 1)*132 + il + g + 8] = acc[it][f][3];
        }
    }
    __syncthreads();

    const float gm = gamma[0];
    for (int idx = tid; idx < 128*128; idx += 256) {
        int m = idx >> 7, i = idx & 127;
        size_t gi = (size_t)(b*MM + mbase + m)*NN + ibase + i;
        out[gi] = gm * x[gi] + sO[m*132 + i] * sInv[i];
    }
}

// ---------------------------------------------------------------------------
extern "C" void kernel_launch(void* const* d_in, const int* in_sizes, int n_in,
                              void* d_out, int out_size)
{
    const float* x     = (const float*)d_in[0];
    const float* Wk    = (const float*)d_in[1];
    const float* bk    = (const float*)d_in[2];
    const float* Wq    = (const float*)d_in[3];
    const float* bq    = (const float*)d_in[4];
    const float* Wv    = (const float*)d_in[5];
    const float* bv    = (const float*)d_in[6];
    const float* gamma = (const float*)d_in[7];
    float* out = (float*)d_out;

    cudaFuncSetAttribute(rsa_qk_kernel,
                         cudaFuncAttributeMaxDynamicSharedMemorySize, QK_SMEM);
    cudaFuncSetAttribute(rsa_pv_kernel,
                         cudaFuncAttributeMaxDynamicSharedMemorySize, PVF_SMEM);

    rsa_proj_kernel<<<BB*DD*16, 256>>>(x, Wk, bk, Wq, bq, Wv, bv);

    dim3 gqk(32, 4, BB);
    rsa_qk_kernel<<<gqk, 256, QK_SMEM>>>();

    dim3 gpv(32, 4, BB);
    rsa_pv_kernel<<<gpv, 256, PVF_SMEM>>>(x, gamma, out);
}